// round 5
// baseline (speedup 1.0000x reference)
#include <cuda_runtime.h>

// ---------------------------------------------------------------------------
// CurveChannel, single kernel, barrier-free, full-occupancy.
// out[b,0,h,w] = clamp( sum_c sum_p conv_w[c]*slopes[p,c]*relu(x[b,c,h,w]
//                       - shift[p,c]) + conv_b, 0, 1 )
//
// Warp-level param compaction (ballot + shfl, no smem/barriers), three
// front-batched independent LDG.128 per thread, and __launch_bounds__(256,8)
// to force 32 regs -> 8 CTAs/SM (100% occupancy) for latency hiding.
// ---------------------------------------------------------------------------

#define NPTS   16
#define IN_CH  3
#define HW4    (512 * 512 / 4)   // float4 groups per (b,c) plane = 65536
#define TPB    256

__global__ __launch_bounds__(TPB, 8) void curve_fused(
    const float* __restrict__ x,       // (8, 3, 512, 512)
    const float* __restrict__ shift,   // (NPTS, C)
    const float* __restrict__ slopes,  // (NPTS, C)
    const float* __restrict__ conv_w,  // (C,)
    const float* __restrict__ conv_b,  // (1,)
    float* __restrict__ out)           // (8, 1, 512, 512)
{
    const int tid  = threadIdx.x;
    const int lane = tid & 31;

    // ---- param loads first (few cache lines, warp-coalesced) ----
    const bool pl = (lane < NPTS);
    float sl0 = pl ? __ldg(&slopes[lane * IN_CH + 0]) : 0.0f;
    float sl1 = pl ? __ldg(&slopes[lane * IN_CH + 1]) : 0.0f;
    float sl2 = pl ? __ldg(&slopes[lane * IN_CH + 2]) : 0.0f;
    float sh0 = pl ? __ldg(&shift [lane * IN_CH + 0]) : 0.0f;
    float sh1 = pl ? __ldg(&shift [lane * IN_CH + 1]) : 0.0f;
    float sh2 = pl ? __ldg(&shift [lane * IN_CH + 2]) : 0.0f;
    const float w0   = __ldg(&conv_w[0]);
    const float w1   = __ldg(&conv_w[1]);
    const float w2   = __ldg(&conv_w[2]);
    const float bias = __ldg(&conv_b[0]);

    // ---- front-batch the three independent x loads (streaming) ----
    const int g = blockIdx.x * TPB + tid;     // [0, 8*HW4)
    const int b = g >> 16;                    // g / HW4
    const int v = g & (HW4 - 1);              // g % HW4
    const float4* xb = reinterpret_cast<const float4*>(x) +
                       (size_t)b * (IN_CH * HW4) + v;

    float4 xv0 = __ldcs(&xb[0 * HW4]);
    float4 xv1 = __ldcs(&xb[1 * HW4]);
    float4 xv2 = __ldcs(&xb[2 * HW4]);

    // ---- active-point masks (overlaps x-load latency) ----
    unsigned m0 = __ballot_sync(0xFFFFFFFFu, sl0 != 0.0f);
    unsigned m1 = __ballot_sync(0xFFFFFFFFu, sl1 != 0.0f);
    unsigned m2 = __ballot_sync(0xFFFFFFFFu, sl2 != 0.0f);

    float4 acc = make_float4(bias, bias, bias, bias);

    while (m0) {
        int src = __ffs(m0) - 1; m0 &= m0 - 1;
        float sh = __shfl_sync(0xFFFFFFFFu, sh0, src);
        float ws = __shfl_sync(0xFFFFFFFFu, sl0, src) * w0;
        acc.x = fmaf(ws, fmaxf(xv0.x - sh, 0.0f), acc.x);
        acc.y = fmaf(ws, fmaxf(xv0.y - sh, 0.0f), acc.y);
        acc.z = fmaf(ws, fmaxf(xv0.z - sh, 0.0f), acc.z);
        acc.w = fmaf(ws, fmaxf(xv0.w - sh, 0.0f), acc.w);
    }
    while (m1) {
        int src = __ffs(m1) - 1; m1 &= m1 - 1;
        float sh = __shfl_sync(0xFFFFFFFFu, sh1, src);
        float ws = __shfl_sync(0xFFFFFFFFu, sl1, src) * w1;
        acc.x = fmaf(ws, fmaxf(xv1.x - sh, 0.0f), acc.x);
        acc.y = fmaf(ws, fmaxf(xv1.y - sh, 0.0f), acc.y);
        acc.z = fmaf(ws, fmaxf(xv1.z - sh, 0.0f), acc.z);
        acc.w = fmaf(ws, fmaxf(xv1.w - sh, 0.0f), acc.w);
    }
    while (m2) {
        int src = __ffs(m2) - 1; m2 &= m2 - 1;
        float sh = __shfl_sync(0xFFFFFFFFu, sh2, src);
        float ws = __shfl_sync(0xFFFFFFFFu, sl2, src) * w2;
        acc.x = fmaf(ws, fmaxf(xv2.x - sh, 0.0f), acc.x);
        acc.y = fmaf(ws, fmaxf(xv2.y - sh, 0.0f), acc.y);
        acc.z = fmaf(ws, fmaxf(xv2.z - sh, 0.0f), acc.z);
        acc.w = fmaf(ws, fmaxf(xv2.w - sh, 0.0f), acc.w);
    }

    acc.x = fminf(fmaxf(acc.x, 0.0f), 1.0f);
    acc.y = fminf(fmaxf(acc.y, 0.0f), 1.0f);
    acc.z = fminf(fmaxf(acc.z, 0.0f), 1.0f);
    acc.w = fminf(fmaxf(acc.w, 0.0f), 1.0f);

    __stcs(&reinterpret_cast<float4*>(out)[g], acc);
}

extern "C" void kernel_launch(void* const* d_in, const int* in_sizes, int n_in,
                              void* d_out, int out_size)
{
    const float* x      = (const float*)d_in[0];
    const float* shift  = (const float*)d_in[1];
    const float* slopes = (const float*)d_in[2];
    const float* conv_w = (const float*)d_in[3];
    const float* conv_b = (const float*)d_in[4];
    float* out = (float*)d_out;

    const int total_groups = out_size / 4;    // 524288
    const int blocks = total_groups / TPB;    // 2048
    curve_fused<<<blocks, TPB>>>(x, shift, slopes, conv_w, conv_b, out);
}

// round 6
// speedup vs baseline: 1.4815x; 1.4815x over previous
#include <cuda_runtime.h>
#include <cstdint>

// ---------------------------------------------------------------------------
// CurveChannel via cp.async.bulk (TMA/UBLKCP) pipelined streaming.
//
// Each CTA owns 1024 contiguous float4 output groups of one batch plane,
// split into 4 stages x 256 groups. tid0 issues all 12 bulk copies (3
// channels x 4 stages, 4KB each) up-front against 4 mbarriers; warps then
// consume stage-by-stage from smem. Loads are fire-and-forget on the TMA
// pipe, so DRAM bytes-in-flight no longer depend on warp count / scoreboard.
// Params are compacted per-warp with ballot+shfl (no extra barriers).
// ---------------------------------------------------------------------------

#define NPTS   16
#define IN_CH  3
#define HW4    (512 * 512 / 4)        // float4 groups per (b,c) plane
#define TPB    256
#define STAGES 4
#define GPS    256                    // float4 groups / channel / stage
#define STAGE_CH_BYTES (GPS * 16)     // 4096
#define STAGE_BYTES (IN_CH * STAGE_CH_BYTES)  // 12288
#define GPC    (STAGES * GPS)         // groups per CTA = 1024
#define BLOCKS_PER_BATCH (HW4 / GPC)  // 64
#define SMEM_MBAR 0
#define SMEM_DATA 64
#define SMEM_TOTAL (SMEM_DATA + STAGES * STAGE_BYTES)  // 49216

__device__ __forceinline__ uint32_t smem_u32(const void* p) {
    uint32_t a;
    asm("{ .reg .u64 t; cvta.to.shared.u64 t, %1; cvt.u32.u64 %0, t; }"
        : "=r"(a) : "l"(p));
    return a;
}

__device__ __forceinline__ void mbar_init(uint32_t mbar, uint32_t count) {
    asm volatile("mbarrier.init.shared.b64 [%0], %1;" :: "r"(mbar), "r"(count) : "memory");
}

__device__ __forceinline__ void mbar_expect_tx(uint32_t mbar, uint32_t bytes) {
    asm volatile("mbarrier.arrive.expect_tx.shared.b64 _, [%0], %1;"
                 :: "r"(mbar), "r"(bytes) : "memory");
}

__device__ __forceinline__ void bulk_ld(uint32_t dst_smem, const void* src, uint32_t bytes,
                                        uint32_t mbar) {
    asm volatile("cp.async.bulk.shared::cluster.global.mbarrier::complete_tx::bytes "
                 "[%0], [%1], %2, [%3];"
                 :: "r"(dst_smem), "l"(src), "r"(bytes), "r"(mbar) : "memory");
}

__device__ __forceinline__ void mbar_wait(uint32_t mbar, uint32_t parity) {
    uint32_t done;
    asm volatile(
        "{\n\t.reg .pred p;\n\t"
        "mbarrier.try_wait.parity.acquire.cta.shared::cta.b64 p, [%1], %2;\n\t"
        "selp.b32 %0, 1, 0, p;\n\t}"
        : "=r"(done) : "r"(mbar), "r"(parity) : "memory");
    if (!done) {
        asm volatile(
            "{\n\t.reg .pred P1;\n\t"
            "W_%=:\n\t"
            "mbarrier.try_wait.parity.acquire.cta.shared::cta.b64 P1, [%0], %1, 0x989680;\n\t"
            "@P1 bra.uni D_%=;\n\t"
            "bra.uni W_%=;\n\t"
            "D_%=:\n\t}"
            :: "r"(mbar), "r"(parity) : "memory");
    }
}

__global__ __launch_bounds__(TPB) void curve_tma(
    const float* __restrict__ x,       // (8, 3, 512, 512)
    const float* __restrict__ shift,   // (NPTS, C)
    const float* __restrict__ slopes,  // (NPTS, C)
    const float* __restrict__ conv_w,  // (C,)
    const float* __restrict__ conv_b,  // (1,)
    float* __restrict__ out)           // (8, 1, 512, 512)
{
    extern __shared__ char smem[];
    const uint32_t sb  = smem_u32(smem);
    const int tid  = threadIdx.x;
    const int lane = tid & 31;

    const int b   = blockIdx.x / BLOCKS_PER_BATCH;
    const int seg = blockIdx.x % BLOCKS_PER_BATCH;
    const float4* xp = reinterpret_cast<const float4*>(x) +
                       (size_t)b * (IN_CH * HW4) + (size_t)seg * GPC;

    // ---- init barriers, then fire ALL bulk copies from tid0 ----
    if (tid == 0) {
        #pragma unroll
        for (int s = 0; s < STAGES; ++s)
            mbar_init(sb + SMEM_MBAR + 8 * s, 1);
    }
    __syncthreads();

    if (tid == 0) {
        #pragma unroll
        for (int s = 0; s < STAGES; ++s) {
            const uint32_t mbar = sb + SMEM_MBAR + 8 * s;
            mbar_expect_tx(mbar, STAGE_BYTES);
            #pragma unroll
            for (int c = 0; c < IN_CH; ++c) {
                bulk_ld(sb + SMEM_DATA + (s * IN_CH + c) * STAGE_CH_BYTES,
                        (const void*)(xp + (size_t)c * HW4 + s * GPS),
                        STAGE_CH_BYTES, mbar);
            }
        }
    }

    // ---- per-warp param compaction (overlaps bulk-copy latency) ----
    const bool pl = (lane < NPTS);
    float sl0 = pl ? __ldg(&slopes[lane * IN_CH + 0]) : 0.0f;
    float sl1 = pl ? __ldg(&slopes[lane * IN_CH + 1]) : 0.0f;
    float sl2 = pl ? __ldg(&slopes[lane * IN_CH + 2]) : 0.0f;
    float sh0 = pl ? __ldg(&shift [lane * IN_CH + 0]) : 0.0f;
    float sh1 = pl ? __ldg(&shift [lane * IN_CH + 1]) : 0.0f;
    float sh2 = pl ? __ldg(&shift [lane * IN_CH + 2]) : 0.0f;
    const float w0   = __ldg(&conv_w[0]);
    const float w1   = __ldg(&conv_w[1]);
    const float w2   = __ldg(&conv_w[2]);
    const float bias = __ldg(&conv_b[0]);

    const unsigned M0 = __ballot_sync(0xFFFFFFFFu, sl0 != 0.0f);
    const unsigned M1 = __ballot_sync(0xFFFFFFFFu, sl1 != 0.0f);
    const unsigned M2 = __ballot_sync(0xFFFFFFFFu, sl2 != 0.0f);

    float4* op = reinterpret_cast<float4*>(out) +
                 (size_t)b * HW4 + (size_t)seg * GPC + tid;

    #pragma unroll
    for (int s = 0; s < STAGES; ++s) {
        mbar_wait(sb + SMEM_MBAR + 8 * s, 0);

        const float4* sp = reinterpret_cast<const float4*>(
            smem + SMEM_DATA + s * STAGE_BYTES);
        const float4 xv0 = sp[0 * GPS + tid];
        const float4 xv1 = sp[1 * GPS + tid];
        const float4 xv2 = sp[2 * GPS + tid];

        float4 acc = make_float4(bias, bias, bias, bias);

        unsigned m0 = M0, m1 = M1, m2 = M2;
        while (m0) {
            int src = __ffs(m0) - 1; m0 &= m0 - 1;
            float sh = __shfl_sync(0xFFFFFFFFu, sh0, src);
            float ws = __shfl_sync(0xFFFFFFFFu, sl0, src) * w0;
            acc.x = fmaf(ws, fmaxf(xv0.x - sh, 0.0f), acc.x);
            acc.y = fmaf(ws, fmaxf(xv0.y - sh, 0.0f), acc.y);
            acc.z = fmaf(ws, fmaxf(xv0.z - sh, 0.0f), acc.z);
            acc.w = fmaf(ws, fmaxf(xv0.w - sh, 0.0f), acc.w);
        }
        while (m1) {
            int src = __ffs(m1) - 1; m1 &= m1 - 1;
            float sh = __shfl_sync(0xFFFFFFFFu, sh1, src);
            float ws = __shfl_sync(0xFFFFFFFFu, sl1, src) * w1;
            acc.x = fmaf(ws, fmaxf(xv1.x - sh, 0.0f), acc.x);
            acc.y = fmaf(ws, fmaxf(xv1.y - sh, 0.0f), acc.y);
            acc.z = fmaf(ws, fmaxf(xv1.z - sh, 0.0f), acc.z);
            acc.w = fmaf(ws, fmaxf(xv1.w - sh, 0.0f), acc.w);
        }
        while (m2) {
            int src = __ffs(m2) - 1; m2 &= m2 - 1;
            float sh = __shfl_sync(0xFFFFFFFFu, sh2, src);
            float ws = __shfl_sync(0xFFFFFFFFu, sl2, src) * w2;
            acc.x = fmaf(ws, fmaxf(xv2.x - sh, 0.0f), acc.x);
            acc.y = fmaf(ws, fmaxf(xv2.y - sh, 0.0f), acc.y);
            acc.z = fmaf(ws, fmaxf(xv2.z - sh, 0.0f), acc.z);
            acc.w = fmaf(ws, fmaxf(xv2.w - sh, 0.0f), acc.w);
        }

        acc.x = fminf(fmaxf(acc.x, 0.0f), 1.0f);
        acc.y = fminf(fmaxf(acc.y, 0.0f), 1.0f);
        acc.z = fminf(fmaxf(acc.z, 0.0f), 1.0f);
        acc.w = fminf(fmaxf(acc.w, 0.0f), 1.0f);

        op[s * GPS] = acc;
    }
}

extern "C" void kernel_launch(void* const* d_in, const int* in_sizes, int n_in,
                              void* d_out, int out_size)
{
    const float* x      = (const float*)d_in[0];
    const float* shift  = (const float*)d_in[1];
    const float* slopes = (const float*)d_in[2];
    const float* conv_w = (const float*)d_in[3];
    const float* conv_b = (const float*)d_in[4];
    float* out = (float*)d_out;

    static bool attr_set = false;
    if (!attr_set) {
        cudaFuncSetAttribute(curve_tma,
                             cudaFuncAttributeMaxDynamicSharedMemorySize,
                             SMEM_TOTAL);
        attr_set = true;
    }

    const int total_groups = out_size / 4;       // 524288
    const int blocks = total_groups / GPC;       // 512
    curve_tma<<<blocks, TPB, SMEM_TOTAL>>>(x, shift, slopes, conv_w, conv_b, out);
}